// round 1
// baseline (speedup 1.0000x reference)
#include <cuda_runtime.h>
#include <math.h>
#include <stdint.h>

// Problem constants
#define BB 2
#define CC 128
#define NN 6000
#define MM 1500
#define HH 4
#define DHH 32

// ---------------- scratch (static device globals; no allocation) ----------------
__device__ float g_Q  [BB*CC*NN];
__device__ float g_K  [BB*CC*NN];
__device__ float g_V  [BB*CC*NN];
__device__ float g_AO [BB*CC*NN];
__device__ float g_ADD[BB*CC*NN];
__device__ float g_Hb [BB*2*CC*NN];
__device__ float g_F1 [BB*CC*MM];
__device__ float g_F2 [BB*CC*MM];
__device__ float g_XH [BB*CC*NN];
__device__ float g_T1 [BB*64*NN];
__device__ float g_T2 [BB*16*NN];
__device__ float g_T3 [BB*4*NN];

// ---------------- tiled fp32 GEMM for 1x1 conv ----------------
// Y[b,o,n] = sum_c W[o,c] * X[b,c,n] (+bias) (opt: *scale+shift, relu, +resid)
// X is split across two pointers: c < split -> X1, else X2 (for concat inputs).
#define GBM 64
#define GBN 64
#define GBK 32

__global__ void conv_gemm(const float* __restrict__ W, const float* __restrict__ bias,
                          const float* __restrict__ X1, const float* __restrict__ X2, int split,
                          float* __restrict__ Y,
                          int Cout, int Cin, int Nlen,
                          const float* __restrict__ scale, const float* __restrict__ shift,
                          int do_relu, const float* __restrict__ resid)
{
    __shared__ float Ws[GBK][GBM];
    __shared__ float Xs[GBK][GBN + 1];

    const int b   = blockIdx.z;
    const int om0 = blockIdx.y * GBM;
    const int n0  = blockIdx.x * GBN;
    const int tid = threadIdx.x;      // 256
    const int tx  = tid & 15;
    const int ty  = tid >> 4;

    float acc[4][4];
#pragma unroll
    for (int i = 0; i < 4; i++)
#pragma unroll
        for (int j = 0; j < 4; j++) acc[i][j] = 0.f;

    for (int k0 = 0; k0 < Cin; k0 += GBK) {
        // load W tile -> Ws[kk][o]
        for (int i = tid; i < GBM * GBK; i += 256) {
            int o  = i / GBK;
            int kk = i % GBK;
            float w = 0.f;
            if (om0 + o < Cout) w = W[(size_t)(om0 + o) * Cin + k0 + kk];
            Ws[kk][o] = w;
        }
        // load X tile -> Xs[kk][n]
        for (int i = tid; i < GBK * GBN; i += 256) {
            int kk = i / GBN;
            int n  = i % GBN;
            int c  = k0 + kk;
            int nn = n0 + n;
            float xv = 0.f;
            if (nn < Nlen) {
                if (c < split) xv = X1[((size_t)b * split + c) * Nlen + nn];
                else           xv = X2[((size_t)b * (Cin - split) + (c - split)) * Nlen + nn];
            }
            Xs[kk][n] = xv;
        }
        __syncthreads();
#pragma unroll
        for (int kk = 0; kk < GBK; kk++) {
            float rw[4], rx[4];
#pragma unroll
            for (int i = 0; i < 4; i++) rw[i] = Ws[kk][ty * 4 + i];
#pragma unroll
            for (int j = 0; j < 4; j++) rx[j] = Xs[kk][tx * 4 + j];
#pragma unroll
            for (int i = 0; i < 4; i++)
#pragma unroll
                for (int j = 0; j < 4; j++) acc[i][j] += rw[i] * rx[j];
        }
        __syncthreads();
    }

#pragma unroll
    for (int i = 0; i < 4; i++) {
        int o = om0 + ty * 4 + i;
        if (o >= Cout) continue;
        float bi = bias  ? bias[o]  : 0.f;
        float sc = scale ? scale[o] : 1.f;
        float sh = shift ? shift[o] : 0.f;
#pragma unroll
        for (int j = 0; j < 4; j++) {
            int nn = n0 + tx * 4 + j;
            if (nn >= Nlen) continue;
            float yv = acc[i][j] + bi;
            yv = yv * sc + sh;
            if (do_relu) yv = fmaxf(yv, 0.f);
            if (resid) yv += resid[((size_t)b * Cout + o) * Nlen + nn];
            Y[((size_t)b * Cout + o) * Nlen + nn] = yv;
        }
    }
}

// ---------------- flash attention (fp32, online softmax) ----------------
// Q,K,V,O layout: [B, C=H*DH, Nq/Nk], channel = h*32 + d.
// maskLogits (may be null): [B, Nk]; masked (<=0) positions get raw QK = -1e6
// BEFORE the 1/sqrt(DH) scaling, matching the reference.
#define FBQ 64
#define FBK 64

__global__ void flash_attn(const float* __restrict__ Q, const float* __restrict__ K,
                           const float* __restrict__ V, const float* __restrict__ maskLogits,
                           float* __restrict__ O, int Nq, int Nk)
{
    __shared__ float qs[DHH][FBQ];
    __shared__ float ks[DHH][FBK + 1];
    __shared__ float vs[DHH][FBK + 1];
    __shared__ float ps[FBQ][FBK + 1];

    const int bh = blockIdx.y;        // b*H + h
    const int b  = bh / HH;
    const int h  = bh % HH;
    const int q0 = blockIdx.x * FBQ;
    const int tid = threadIdx.x;      // 256
    const int tx = tid & 15;
    const int ty = tid >> 4;
    const float sm_scale = 0.17677669529663687f;  // 1/sqrt(32)

    const float* Qb = Q + ((size_t)b * CC + h * DHH) * Nq;
    const float* Kb = K + ((size_t)b * CC + h * DHH) * Nk;
    const float* Vb = V + ((size_t)b * CC + h * DHH) * Nk;

    for (int i = tid; i < DHH * FBQ; i += 256) {
        int d = i / FBQ, r = i % FBQ;
        int nn = q0 + r;
        qs[d][r] = (nn < Nq) ? Qb[(size_t)d * Nq + nn] : 0.f;
    }

    float m[4], l[4], acc[4][2];
#pragma unroll
    for (int i = 0; i < 4; i++) { m[i] = -3.0e38f; l[i] = 0.f; acc[i][0] = 0.f; acc[i][1] = 0.f; }

    for (int k0 = 0; k0 < Nk; k0 += FBK) {
        for (int i = tid; i < DHH * FBK; i += 256) {
            int d = i / FBK, c = i % FBK;
            int nn = k0 + c;
            float kv = 0.f, vv = 0.f;
            if (nn < Nk) { kv = Kb[(size_t)d * Nk + nn]; vv = Vb[(size_t)d * Nk + nn]; }
            ks[d][c] = kv;
            vs[d][c] = vv;
        }
        __syncthreads();

        // S = Q^T K  (rows = queries 4*ty.., cols = keys 4*tx..)
        float s[4][4];
#pragma unroll
        for (int i = 0; i < 4; i++)
#pragma unroll
            for (int j = 0; j < 4; j++) s[i][j] = 0.f;
#pragma unroll
        for (int d = 0; d < DHH; d++) {
            float rq[4], rk[4];
#pragma unroll
            for (int i = 0; i < 4; i++) rq[i] = qs[d][ty * 4 + i];
#pragma unroll
            for (int j = 0; j < 4; j++) rk[j] = ks[d][tx * 4 + j];
#pragma unroll
            for (int i = 0; i < 4; i++)
#pragma unroll
                for (int j = 0; j < 4; j++) s[i][j] += rq[i] * rk[j];
        }

        // mask (before scale) + scale; padding -> huge negative so exp==0
#pragma unroll
        for (int j = 0; j < 4; j++) {
            int nn = k0 + tx * 4 + j;
            bool valid = nn < Nk;
            bool keep = valid;
            if (valid && maskLogits) keep = (maskLogits[(size_t)b * Nk + nn] > 0.f);
#pragma unroll
            for (int i = 0; i < 4; i++) {
                float val;
                if (keep)       val = s[i][j] * sm_scale;
                else if (valid) val = -1.0e6f * sm_scale;   // matches reference masked_fill
                else            val = -3.0e38f;             // padding: exp -> 0
                s[i][j] = val;
            }
        }

        // online softmax update (row reductions across the 16-lane tx group)
#pragma unroll
        for (int i = 0; i < 4; i++) {
            float mx = fmaxf(fmaxf(s[i][0], s[i][1]), fmaxf(s[i][2], s[i][3]));
#pragma unroll
            for (int off = 8; off >= 1; off >>= 1)
                mx = fmaxf(mx, __shfl_xor_sync(0xffffffffu, mx, off, 16));
            float mnew = fmaxf(m[i], mx);
            float corr = __expf(m[i] - mnew);
            float psum = 0.f;
#pragma unroll
            for (int j = 0; j < 4; j++) {
                float p = __expf(s[i][j] - mnew);
                s[i][j] = p;
                psum += p;
            }
#pragma unroll
            for (int off = 8; off >= 1; off >>= 1)
                psum += __shfl_xor_sync(0xffffffffu, psum, off, 16);
            l[i] = l[i] * corr + psum;
            m[i] = mnew;
            acc[i][0] *= corr;
            acc[i][1] *= corr;
#pragma unroll
            for (int j = 0; j < 4; j++) ps[ty * 4 + i][tx * 4 + j] = s[i][j];
        }
        __syncthreads();

        // acc += P @ V^T  (thread owns rows 4*ty.., dims d0,d0+1)
        const int d0 = tx * 2;
#pragma unroll
        for (int i = 0; i < 4; i++) {
            int r = ty * 4 + i;
            float a0 = acc[i][0], a1 = acc[i][1];
#pragma unroll 8
            for (int c = 0; c < FBK; c++) {
                float p = ps[r][c];
                a0 += p * vs[d0][c];
                a1 += p * vs[d0 + 1][c];
            }
            acc[i][0] = a0; acc[i][1] = a1;
        }
        __syncthreads();
    }

    float* Ob = O + ((size_t)b * CC + h * DHH) * Nq;
    const int d0 = tx * 2;
#pragma unroll
    for (int i = 0; i < 4; i++) {
        int r = q0 + ty * 4 + i;
        if (r >= Nq) continue;
        float inv = 1.f / l[i];
        Ob[(size_t)d0 * Nq + r]       = acc[i][0] * inv;
        Ob[(size_t)(d0 + 1) * Nq + r] = acc[i][1] * inv;
    }
}

// ---------------- small conv (Cout small: 16/4/1) ----------------
__global__ void conv_small(const float* __restrict__ W, const float* __restrict__ bias,
                           const float* __restrict__ X, float* __restrict__ Y,
                           int Cout, int Cin, int Nlen)
{
    int idx = blockIdx.x * blockDim.x + threadIdx.x;
    int total = BB * Cout * Nlen;
    if (idx >= total) return;
    int n = idx % Nlen;
    int o = (idx / Nlen) % Cout;
    int b = idx / (Nlen * Cout);
    float acc = bias[o];
    const float* Xb = X + (size_t)b * Cin * Nlen + n;
    const float* Wo = W + (size_t)o * Cin;
    for (int c = 0; c < Cin; c++) acc += Wo[c] * Xb[(size_t)c * Nlen];
    Y[idx] = acc;
}

// ---------------- instance norm (biased var, eps=1e-3) + scale/shift + relu, in place ----------------
__global__ void instnorm_relu(float* __restrict__ X, const float* __restrict__ s,
                              const float* __restrict__ sh, int Cc, int Nlen)
{
    int bc = blockIdx.x;               // b*Cc + c
    int c  = bc % Cc;
    float* x = X + (size_t)bc * Nlen;
    int tid = threadIdx.x;

    float sum = 0.f, sq = 0.f;
    for (int i = tid; i < Nlen; i += blockDim.x) { float v = x[i]; sum += v; sq += v * v; }
#pragma unroll
    for (int off = 16; off >= 1; off >>= 1) {
        sum += __shfl_xor_sync(0xffffffffu, sum, off);
        sq  += __shfl_xor_sync(0xffffffffu, sq,  off);
    }
    __shared__ float ssum[8], ssq[8];
    __shared__ float smu, sinv;
    int w = tid >> 5;
    if ((tid & 31) == 0) { ssum[w] = sum; ssq[w] = sq; }
    __syncthreads();
    if (tid == 0) {
        float S = 0.f, Q2 = 0.f;
        for (int i = 0; i < (int)(blockDim.x >> 5); i++) { S += ssum[i]; Q2 += ssq[i]; }
        float mu  = S / Nlen;
        float var = fmaxf(Q2 / Nlen - mu * mu, 0.f);
        smu  = mu;
        sinv = rsqrtf(var + 1e-3f);
    }
    __syncthreads();
    float scv = s[c] * sinv, mu = smu, shv = sh[c];
    for (int i = tid; i < Nlen; i += blockDim.x) {
        float v = (x[i] - mu) * scv + shv;
        x[i] = fmaxf(v, 0.f);
    }
}

__global__ void add_k(const float* __restrict__ a, const float* __restrict__ b,
                      float* __restrict__ y, int n)
{
    int i = blockIdx.x * blockDim.x + threadIdx.x;
    if (i < n) y[i] = a[i] + b[i];
}

// ---------------- host ----------------
static void run_conv(const float* W, const float* bias,
                     const float* X1, const float* X2, int split,
                     float* Y, int Cout, int Cin, int Nlen,
                     const float* scale, const float* shift, int relu, const float* resid)
{
    dim3 grid((Nlen + GBN - 1) / GBN, (Cout + GBM - 1) / GBM, BB);
    conv_gemm<<<grid, 256>>>(W, bias, X1, X2, split, Y, Cout, Cin, Nlen, scale, shift, relu, resid);
}

extern "C" void kernel_launch(void* const* d_in, const int* in_sizes, int n_in,
                              void* d_out, int out_size)
{
    const float* d_in1      = (const float*)d_in[1];   // d  [B,C,N]
    const float* feat_piece = (const float*)d_in[2];   // [B,C,M]
    const float* logits_in  = (const float*)d_in[3];   // [B,N]
    const float* Wq  = (const float*)d_in[4];
    const float* bq  = (const float*)d_in[5];
    const float* Wk  = (const float*)d_in[6];
    const float* bk  = (const float*)d_in[7];
    const float* Wv  = (const float*)d_in[8];
    const float* bv  = (const float*)d_in[9];
    const float* Wm  = (const float*)d_in[10];
    const float* bm  = (const float*)d_in[11];
    const float* Wc1 = (const float*)d_in[12];
    const float* bc1 = (const float*)d_in[13];
    const float* bns = (const float*)d_in[14];
    const float* bnsh= (const float*)d_in[15];
    const float* Wc2 = (const float*)d_in[16];
    const float* bc2 = (const float*)d_in[17];
    const float* iW1 = (const float*)d_in[18];
    const float* ib1 = (const float*)d_in[19];
    const float* ibn1s  = (const float*)d_in[20];
    const float* ibn1sh = (const float*)d_in[21];
    const float* iW2 = (const float*)d_in[22];
    const float* ib2 = (const float*)d_in[23];
    const float* ibn2s  = (const float*)d_in[24];
    const float* ibn2sh = (const float*)d_in[25];
    const float* iW3 = (const float*)d_in[26];
    const float* ib3 = (const float*)d_in[27];
    const float* ibn3s  = (const float*)d_in[28];
    const float* ibn3sh = (const float*)d_in[29];
    const float* iW4 = (const float*)d_in[30];
    const float* ib4 = (const float*)d_in[31];

    float *Q, *K, *V, *AO, *ADD, *Hb, *F1, *F2, *XH, *T1, *T2, *T3;
    cudaGetSymbolAddress((void**)&Q,   g_Q);
    cudaGetSymbolAddress((void**)&K,   g_K);
    cudaGetSymbolAddress((void**)&V,   g_V);
    cudaGetSymbolAddress((void**)&AO,  g_AO);
    cudaGetSymbolAddress((void**)&ADD, g_ADD);
    cudaGetSymbolAddress((void**)&Hb,  g_Hb);
    cudaGetSymbolAddress((void**)&F1,  g_F1);
    cudaGetSymbolAddress((void**)&F2,  g_F2);
    cudaGetSymbolAddress((void**)&XH,  g_XH);
    cudaGetSymbolAddress((void**)&T1,  g_T1);
    cudaGetSymbolAddress((void**)&T2,  g_T2);
    cudaGetSymbolAddress((void**)&T3,  g_T3);

    auto attn = [&](const float* x1, const float* x2, const float* mask,
                    int Nq, int Nk, int li, float* out, bool resid) {
        const int C2 = 2 * CC;
        run_conv(Wq + (size_t)li * CC * CC, bq + (size_t)li * CC, x1, nullptr, CC,
                 Q, CC, CC, Nq, nullptr, nullptr, 0, nullptr);
        run_conv(Wk + (size_t)li * CC * CC, bk + (size_t)li * CC, x2, nullptr, CC,
                 K, CC, CC, Nk, nullptr, nullptr, 0, nullptr);
        run_conv(Wv + (size_t)li * CC * CC, bv + (size_t)li * CC, x2, nullptr, CC,
                 V, CC, CC, Nk, nullptr, nullptr, 0, nullptr);
        dim3 fg((Nq + FBQ - 1) / FBQ, BB * HH);
        flash_attn<<<fg, 256>>>(Q, K, V, mask, AO, Nq, Nk);
        run_conv(Wm + (size_t)li * CC * CC, bm + (size_t)li * CC, AO, nullptr, CC,
                 ADD, CC, CC, Nq, nullptr, nullptr, 0, nullptr);
        run_conv(Wc1 + (size_t)li * C2 * C2, bc1 + (size_t)li * C2, x1, ADD, CC,
                 Hb, C2, C2, Nq, bns + (size_t)li * C2, bnsh + (size_t)li * C2, 1, nullptr);
        run_conv(Wc2 + (size_t)li * CC * C2, bc2 + (size_t)li * CC, Hb, nullptr, C2,
                 out, CC, C2, Nq, nullptr, nullptr, 0, resid ? x1 : nullptr);
    };

    // layer 0: cluster  (feat_piece <- d, masked kv)
    attn(feat_piece, d_in1, logits_in, MM, NN, 0, F1, true);
    // layer 1: context  (self-attention on feat)
    attn(F1, F1, nullptr, MM, MM, 1, F2, true);
    // layer 2: decluster (d <- feat); keep conv output (== d_new - d_old) in XH
    attn(d_in1, F2, nullptr, NN, MM, 2, XH, false);

    float* dnew   = (float*)d_out;                 // [B,C,N]
    float* logout = dnew + (size_t)BB * CC * NN;   // [B,N]
    {
        int n = BB * CC * NN;
        add_k<<<(n + 255) / 256, 256>>>(d_in1, XH, dnew, n);
    }

    // head on x = d_new - d_old == XH
    run_conv(iW1, ib1, XH, nullptr, CC, T1, 64, CC, NN, nullptr, nullptr, 0, nullptr);
    instnorm_relu<<<BB * 64, 256>>>(T1, ibn1s, ibn1sh, 64, NN);

    conv_small<<<(BB * 16 * NN + 255) / 256, 256>>>(iW2, ib2, T1, T2, 16, 64, NN);
    instnorm_relu<<<BB * 16, 256>>>(T2, ibn2s, ibn2sh, 16, NN);

    conv_small<<<(BB * 4 * NN + 255) / 256, 256>>>(iW3, ib3, T2, T3, 4, 16, NN);
    instnorm_relu<<<BB * 4, 256>>>(T3, ibn3s, ibn3sh, 4, NN);

    conv_small<<<(BB * 1 * NN + 255) / 256, 256>>>(iW4, ib4, T3, logout, 1, 4, NN);
}

// round 3
// speedup vs baseline: 1.9967x; 1.9967x over previous
#include <cuda_runtime.h>
#include <math.h>
#include <stdint.h>

// Problem constants
#define BB 2
#define CC 128
#define NN 6000
#define MM 1500
#define HH 4
#define DHH 32
#define BH (BB*HH)
#define NSPLIT 4

// ---------------- scratch (static device globals; no allocation) ----------------
__device__ float g_Q  [BB*CC*NN];
__device__ float g_K  [BB*CC*NN];
__device__ float g_V  [BB*CC*NN];
__device__ float g_AO [BB*CC*NN];
__device__ float g_ADD[BB*CC*NN];
__device__ float g_Hb [BB*2*CC*NN];
__device__ float g_F1 [BB*CC*MM];
__device__ float g_F2 [BB*CC*MM];
__device__ float g_XH [BB*CC*NN];
__device__ float g_T1 [BB*64*NN];
__device__ float g_T2 [BB*16*NN];
__device__ float g_T3 [BB*4*NN];
// split-KV partials
__device__ float g_OP [NSPLIT*BH*DHH*NN];
__device__ float g_MP [NSPLIT*BH*NN];
__device__ float g_LP [NSPLIT*BH*NN];

// ---------------- tiled fp32 GEMM for 1x1 conv ----------------
#define GBM 64
#define GBN 64
#define GBK 32

__global__ void conv_gemm(const float* __restrict__ W, const float* __restrict__ bias,
                          const float* __restrict__ X1, const float* __restrict__ X2, int split,
                          float* __restrict__ Y, float* __restrict__ Ypre,
                          int Cout, int Cin, int Nlen,
                          const float* __restrict__ scale, const float* __restrict__ shift,
                          int do_relu, const float* __restrict__ resid)
{
    __shared__ float Ws[GBK][GBM + 4];
    __shared__ float Xs[GBK][GBN];

    const int b   = blockIdx.z;
    const int om0 = blockIdx.y * GBM;
    const int n0  = blockIdx.x * GBN;
    const int tid = threadIdx.x;      // 256
    const int tx  = tid & 15;
    const int ty  = tid >> 4;

    float acc[4][4];
#pragma unroll
    for (int i = 0; i < 4; i++)
#pragma unroll
        for (int j = 0; j < 4; j++) acc[i][j] = 0.f;

    for (int k0 = 0; k0 < Cin; k0 += GBK) {
        // W tile: global [o][kk] -> Ws[kk][o], float4 global loads
        for (int i = tid; i < GBM * (GBK / 4); i += 256) {
            int o  = i / (GBK / 4);
            int k4 = i % (GBK / 4);
            float4 w = make_float4(0.f, 0.f, 0.f, 0.f);
            if (om0 + o < Cout)
                w = *(const float4*)&W[(size_t)(om0 + o) * Cin + k0 + k4 * 4];
            Ws[k4 * 4 + 0][o] = w.x;
            Ws[k4 * 4 + 1][o] = w.y;
            Ws[k4 * 4 + 2][o] = w.z;
            Ws[k4 * 4 + 3][o] = w.w;
        }
        // X tile: float4 loads (Nlen % 4 == 0 for all call sites)
        for (int i = tid; i < GBK * (GBN / 4); i += 256) {
            int kk = i / (GBN / 4);
            int n4 = i % (GBN / 4);
            int c  = k0 + kk;
            int nn = n0 + n4 * 4;
            float4 xv = make_float4(0.f, 0.f, 0.f, 0.f);
            if (nn < Nlen) {
                if (c < split) xv = *(const float4*)&X1[((size_t)b * split + c) * Nlen + nn];
                else           xv = *(const float4*)&X2[((size_t)b * (Cin - split) + (c - split)) * Nlen + nn];
            }
            *(float4*)&Xs[kk][n4 * 4] = xv;
        }
        __syncthreads();
#pragma unroll
        for (int kk = 0; kk < GBK; kk++) {
            float4 rw = *(const float4*)&Ws[kk][ty * 4];
            float4 rx = *(const float4*)&Xs[kk][tx * 4];
            acc[0][0] += rw.x * rx.x; acc[0][1] += rw.x * rx.y; acc[0][2] += rw.x * rx.z; acc[0][3] += rw.x * rx.w;
            acc[1][0] += rw.y * rx.x; acc[1][1] += rw.y * rx.y; acc[1][2] += rw.y * rx.z; acc[1][3] += rw.y * rx.w;
            acc[2][0] += rw.z * rx.x; acc[2][1] += rw.z * rx.y; acc[2][2] += rw.z * rx.z; acc[2][3] += rw.z * rx.w;
            acc[3][0] += rw.w * rx.x; acc[3][1] += rw.w * rx.y; acc[3][2] += rw.w * rx.z; acc[3][3] += rw.w * rx.w;
        }
        __syncthreads();
    }

    const int nn0 = n0 + tx * 4;
#pragma unroll
    for (int i = 0; i < 4; i++) {
        int o = om0 + ty * 4 + i;
        if (o >= Cout) continue;
        float bi = bias  ? bias[o]  : 0.f;
        float sc = scale ? scale[o] : 1.f;
        float sh = shift ? shift[o] : 0.f;
        if (nn0 >= Nlen) continue;
        float4 yv;
        yv.x = (acc[i][0] + bi) * sc + sh;
        yv.y = (acc[i][1] + bi) * sc + sh;
        yv.z = (acc[i][2] + bi) * sc + sh;
        yv.w = (acc[i][3] + bi) * sc + sh;
        if (do_relu) {
            yv.x = fmaxf(yv.x, 0.f); yv.y = fmaxf(yv.y, 0.f);
            yv.z = fmaxf(yv.z, 0.f); yv.w = fmaxf(yv.w, 0.f);
        }
        size_t off = ((size_t)b * Cout + o) * Nlen + nn0;
        if (Ypre) *(float4*)&Ypre[off] = yv;
        if (resid) {
            float4 rv = *(const float4*)&resid[off];
            yv.x += rv.x; yv.y += rv.y; yv.z += rv.z; yv.w += rv.w;
        }
        *(float4*)&Y[off] = yv;
    }
}

// ---------------- flash attention (fp32, online softmax, split-KV) ----------------
#define FBQ 64
#define FBK 64
#define VPAD 2   // even pad -> float2 loads at even d0 stay 8B aligned

__global__ void flash_attn(const float* __restrict__ Q, const float* __restrict__ K,
                           const float* __restrict__ V, const float* __restrict__ maskLogits,
                           float* __restrict__ O,
                           float* __restrict__ Opart, float* __restrict__ Mpart, float* __restrict__ Lpart,
                           int Nq, int Nk, int nsplit, int kvchunk)
{
    __shared__ float qs[DHH][FBQ];
    __shared__ float ks[DHH][FBK];
    __shared__ float vs[FBK][DHH + VPAD];
    __shared__ float ps[FBQ][FBK];

    const int bh = blockIdx.y;        // b*H + h
    const int b  = bh / HH;
    const int h  = bh % HH;
    const int q0 = blockIdx.x * FBQ;
    const int sp = blockIdx.z;
    const int tid = threadIdx.x;      // 256
    const int tx = tid & 15;
    const int ty = tid >> 4;
    const float sm_scale = 0.17677669529663687f;  // 1/sqrt(32)

    const float* Qb = Q + ((size_t)b * CC + h * DHH) * Nq;
    const float* Kb = K + ((size_t)b * CC + h * DHH) * Nk;
    const float* Vb = V + ((size_t)b * CC + h * DHH) * Nk;

    // load Q tile (float4; Nq % 4 == 0, q0 % 64 == 0)
    for (int i = tid; i < DHH * (FBQ / 4); i += 256) {
        int d  = i / (FBQ / 4);
        int r4 = i % (FBQ / 4);
        int nn = q0 + r4 * 4;
        float4 qv = make_float4(0.f, 0.f, 0.f, 0.f);
        if (nn < Nq) qv = *(const float4*)&Qb[(size_t)d * Nq + nn];
        *(float4*)&qs[d][r4 * 4] = qv;
    }

    float m[4], l[4], acc[4][2];
#pragma unroll
    for (int i = 0; i < 4; i++) { m[i] = -3.0e38f; l[i] = 0.f; acc[i][0] = 0.f; acc[i][1] = 0.f; }

    const int kvbeg = sp * kvchunk;
    const int kvend = min(Nk, kvbeg + kvchunk);

    for (int k0 = kvbeg; k0 < kvend; k0 += FBK) {
        // load K (row layout) and V (transposed to [c][d]) tiles with float4 global loads
        for (int i = tid; i < DHH * (FBK / 4); i += 256) {
            int d  = i / (FBK / 4);
            int c4 = i % (FBK / 4);
            int nn = k0 + c4 * 4;
            float4 kv = make_float4(0.f, 0.f, 0.f, 0.f);
            float4 vv = make_float4(0.f, 0.f, 0.f, 0.f);
            if (nn < Nk) {
                kv = *(const float4*)&Kb[(size_t)d * Nk + nn];
                vv = *(const float4*)&Vb[(size_t)d * Nk + nn];
            }
            *(float4*)&ks[d][c4 * 4] = kv;
            vs[c4 * 4 + 0][d] = vv.x;
            vs[c4 * 4 + 1][d] = vv.y;
            vs[c4 * 4 + 2][d] = vv.z;
            vs[c4 * 4 + 3][d] = vv.w;
        }
        __syncthreads();

        // S = Q^T K
        float s[4][4];
#pragma unroll
        for (int i = 0; i < 4; i++)
#pragma unroll
            for (int j = 0; j < 4; j++) s[i][j] = 0.f;
#pragma unroll
        for (int d = 0; d < DHH; d++) {
            float4 rq = *(const float4*)&qs[d][ty * 4];
            float4 rk = *(const float4*)&ks[d][tx * 4];
            s[0][0] += rq.x * rk.x; s[0][1] += rq.x * rk.y; s[0][2] += rq.x * rk.z; s[0][3] += rq.x * rk.w;
            s[1][0] += rq.y * rk.x; s[1][1] += rq.y * rk.y; s[1][2] += rq.y * rk.z; s[1][3] += rq.y * rk.w;
            s[2][0] += rq.z * rk.x; s[2][1] += rq.z * rk.y; s[2][2] += rq.z * rk.z; s[2][3] += rq.z * rk.w;
            s[3][0] += rq.w * rk.x; s[3][1] += rq.w * rk.y; s[3][2] += rq.w * rk.z; s[3][3] += rq.w * rk.w;
        }

        // mask (before scale) + scale; padding -> -inf
#pragma unroll
        for (int j = 0; j < 4; j++) {
            int nn = k0 + tx * 4 + j;
            bool valid = nn < Nk;
            bool keep = valid;
            if (valid && maskLogits) keep = (maskLogits[(size_t)b * Nk + nn] > 0.f);
#pragma unroll
            for (int i = 0; i < 4; i++) {
                float val;
                if (keep)       val = s[i][j] * sm_scale;
                else if (valid) val = -1.0e6f * sm_scale;
                else            val = -3.0e38f;
                s[i][j] = val;
            }
        }

        // online softmax update
#pragma unroll
        for (int i = 0; i < 4; i++) {
            float mx = fmaxf(fmaxf(s[i][0], s[i][1]), fmaxf(s[i][2], s[i][3]));
#pragma unroll
            for (int off = 8; off >= 1; off >>= 1)
                mx = fmaxf(mx, __shfl_xor_sync(0xffffffffu, mx, off, 16));
            float mnew = fmaxf(m[i], mx);
            float corr = __expf(m[i] - mnew);
            float p0 = __expf(s[i][0] - mnew);
            float p1 = __expf(s[i][1] - mnew);
            float p2 = __expf(s[i][2] - mnew);
            float p3 = __expf(s[i][3] - mnew);
            float psum = p0 + p1 + p2 + p3;
#pragma unroll
            for (int off = 8; off >= 1; off >>= 1)
                psum += __shfl_xor_sync(0xffffffffu, psum, off, 16);
            l[i] = l[i] * corr + psum;
            m[i] = mnew;
            acc[i][0] *= corr;
            acc[i][1] *= corr;
            *(float4*)&ps[ty * 4 + i][tx * 4] = make_float4(p0, p1, p2, p3);
        }
        __syncthreads();

        // acc += P @ V^T : thread owns rows ty*4.., dims d0,d0+1
        const int d0 = tx * 2;
#pragma unroll 4
        for (int c0 = 0; c0 < FBK; c0 += 4) {
            float2 v0 = *(const float2*)&vs[c0 + 0][d0];
            float2 v1 = *(const float2*)&vs[c0 + 1][d0];
            float2 v2 = *(const float2*)&vs[c0 + 2][d0];
            float2 v3 = *(const float2*)&vs[c0 + 3][d0];
#pragma unroll
            for (int i = 0; i < 4; i++) {
                float4 p = *(const float4*)&ps[ty * 4 + i][c0];
                acc[i][0] += p.x * v0.x + p.y * v1.x + p.z * v2.x + p.w * v3.x;
                acc[i][1] += p.x * v0.y + p.y * v1.y + p.z * v2.y + p.w * v3.y;
            }
        }
        __syncthreads();
    }

    const int d0 = tx * 2;
    if (nsplit == 1) {
        float* Ob = O + ((size_t)b * CC + h * DHH) * Nq;
#pragma unroll
        for (int i = 0; i < 4; i++) {
            int r = q0 + ty * 4 + i;
            if (r >= Nq) continue;
            float inv = 1.f / l[i];
            Ob[(size_t)d0 * Nq + r]       = acc[i][0] * inv;
            Ob[(size_t)(d0 + 1) * Nq + r] = acc[i][1] * inv;
        }
    } else {
        float* Op = Opart + (((size_t)sp * BH + bh) * DHH) * Nq;
#pragma unroll
        for (int i = 0; i < 4; i++) {
            int r = q0 + ty * 4 + i;
            if (r >= Nq) continue;
            Op[(size_t)d0 * Nq + r]       = acc[i][0];
            Op[(size_t)(d0 + 1) * Nq + r] = acc[i][1];
            if (tx == 0) {
                Mpart[((size_t)sp * BH + bh) * Nq + r] = m[i];
                Lpart[((size_t)sp * BH + bh) * Nq + r] = l[i];
            }
        }
    }
}

__global__ void flash_combine(const float* __restrict__ Opart, const float* __restrict__ Mpart,
                              const float* __restrict__ Lpart, float* __restrict__ O,
                              int Nq, int nsplit)
{
    int idx = blockIdx.x * blockDim.x + threadIdx.x;
    if (idx >= BH * Nq) return;
    int n  = idx % Nq;
    int bh = idx / Nq;
    int b  = bh / HH;
    int h  = bh % HH;

    float M = -3.0e38f;
    for (int s = 0; s < nsplit; s++)
        M = fmaxf(M, Mpart[((size_t)s * BH + bh) * Nq + n]);
    float w[NSPLIT];
    float L = 0.f;
    for (int s = 0; s < nsplit; s++) {
        float ws = __expf(Mpart[((size_t)s * BH + bh) * Nq + n] - M);
        w[s] = ws;
        L += ws * Lpart[((size_t)s * BH + bh) * Nq + n];
    }
    float inv = 1.f / L;
    float* Ob = O + ((size_t)b * CC + h * DHH) * Nq + n;
    for (int d = 0; d < DHH; d++) {
        float acc = 0.f;
        for (int s = 0; s < nsplit; s++)
            acc += w[s] * Opart[(((size_t)s * BH + bh) * DHH + d) * Nq + n];
        Ob[(size_t)d * Nq] = acc * inv;
    }
}

// ---------------- small conv (Cout small: 16/4/1) ----------------
__global__ void conv_small(const float* __restrict__ W, const float* __restrict__ bias,
                           const float* __restrict__ X, float* __restrict__ Y,
                           int Cout, int Cin, int Nlen)
{
    int idx = blockIdx.x * blockDim.x + threadIdx.x;
    int total = BB * Cout * Nlen;
    if (idx >= total) return;
    int n = idx % Nlen;
    int o = (idx / Nlen) % Cout;
    int b = idx / (Nlen * Cout);
    float acc = bias[o];
    const float* Xb = X + (size_t)b * Cin * Nlen + n;
    const float* Wo = W + (size_t)o * Cin;
    for (int c = 0; c < Cin; c++) acc += Wo[c] * Xb[(size_t)c * Nlen];
    Y[idx] = acc;
}

// ---------------- instance norm + scale/shift + relu, in place ----------------
__global__ void instnorm_relu(float* __restrict__ X, const float* __restrict__ s,
                              const float* __restrict__ sh, int Cc, int Nlen)
{
    int bc = blockIdx.x;
    int c  = bc % Cc;
    float* x = X + (size_t)bc * Nlen;
    int tid = threadIdx.x;

    float sum = 0.f, sq = 0.f;
    for (int i = tid; i < Nlen; i += blockDim.x) { float v = x[i]; sum += v; sq += v * v; }
#pragma unroll
    for (int off = 16; off >= 1; off >>= 1) {
        sum += __shfl_xor_sync(0xffffffffu, sum, off);
        sq  += __shfl_xor_sync(0xffffffffu, sq,  off);
    }
    __shared__ float ssum[8], ssq[8];
    __shared__ float smu, sinv;
    int w = tid >> 5;
    if ((tid & 31) == 0) { ssum[w] = sum; ssq[w] = sq; }
    __syncthreads();
    if (tid == 0) {
        float S = 0.f, Q2 = 0.f;
        for (int i = 0; i < (int)(blockDim.x >> 5); i++) { S += ssum[i]; Q2 += ssq[i]; }
        float mu  = S / Nlen;
        float var = fmaxf(Q2 / Nlen - mu * mu, 0.f);
        smu  = mu;
        sinv = rsqrtf(var + 1e-3f);
    }
    __syncthreads();
    float scv = s[c] * sinv, mu = smu, shv = sh[c];
    for (int i = tid; i < Nlen; i += blockDim.x) {
        float v = (x[i] - mu) * scv + shv;
        x[i] = fmaxf(v, 0.f);
    }
}

// ---------------- host ----------------
static void run_conv(const float* W, const float* bias,
                     const float* X1, const float* X2, int split,
                     float* Y, float* Ypre, int Cout, int Cin, int Nlen,
                     const float* scale, const float* shift, int relu, const float* resid)
{
    dim3 grid((Nlen + GBN - 1) / GBN, (Cout + GBM - 1) / GBM, BB);
    conv_gemm<<<grid, 256>>>(W, bias, X1, X2, split, Y, Ypre, Cout, Cin, Nlen, scale, shift, relu, resid);
}

extern "C" void kernel_launch(void* const* d_in, const int* in_sizes, int n_in,
                              void* d_out, int out_size)
{
    const float* d_in1      = (const float*)d_in[1];
    const float* feat_piece = (const float*)d_in[2];
    const float* logits_in  = (const float*)d_in[3];
    const float* Wq  = (const float*)d_in[4];
    const float* bq  = (const float*)d_in[5];
    const float* Wk  = (const float*)d_in[6];
    const float* bk  = (const float*)d_in[7];
    const float* Wv  = (const float*)d_in[8];
    const float* bv  = (const float*)d_in[9];
    const float* Wm  = (const float*)d_in[10];
    const float* bm  = (const float*)d_in[11];
    const float* Wc1 = (const float*)d_in[12];
    const float* bc1 = (const float*)d_in[13];
    const float* bns = (const float*)d_in[14];
    const float* bnsh= (const float*)d_in[15];
    const float* Wc2 = (const float*)d_in[16];
    const float* bc2 = (const float*)d_in[17];
    const float* iW1 = (const float*)d_in[18];
    const float* ib1 = (const float*)d_in[19];
    const float* ibn1s  = (const float*)d_in[20];
    const float* ibn1sh = (const float*)d_in[21];
    const float* iW2 = (const float*)d_in[22];
    const float* ib2 = (const float*)d_in[23];
    const float* ibn2s  = (const float*)d_in[24];
    const float* ibn2sh = (const float*)d_in[25];
    const float* iW3 = (const float*)d_in[26];
    const float* ib3 = (const float*)d_in[27];
    const float* ibn3s  = (const float*)d_in[28];
    const float* ibn3sh = (const float*)d_in[29];
    const float* iW4 = (const float*)d_in[30];
    const float* ib4 = (const float*)d_in[31];

    float *Q, *K, *V, *AO, *ADD, *Hb, *F1, *F2, *XH, *T1, *T2, *T3, *OP, *MP, *LP;
    cudaGetSymbolAddress((void**)&Q,   g_Q);
    cudaGetSymbolAddress((void**)&K,   g_K);
    cudaGetSymbolAddress((void**)&V,   g_V);
    cudaGetSymbolAddress((void**)&AO,  g_AO);
    cudaGetSymbolAddress((void**)&ADD, g_ADD);
    cudaGetSymbolAddress((void**)&Hb,  g_Hb);
    cudaGetSymbolAddress((void**)&F1,  g_F1);
    cudaGetSymbolAddress((void**)&F2,  g_F2);
    cudaGetSymbolAddress((void**)&XH,  g_XH);
    cudaGetSymbolAddress((void**)&T1,  g_T1);
    cudaGetSymbolAddress((void**)&T2,  g_T2);
    cudaGetSymbolAddress((void**)&T3,  g_T3);
    cudaGetSymbolAddress((void**)&OP,  g_OP);
    cudaGetSymbolAddress((void**)&MP,  g_MP);
    cudaGetSymbolAddress((void**)&LP,  g_LP);

    auto attn = [&](const float* x1, const float* x2, const float* mask,
                    int Nq, int Nk, int li, float* out, float* outPre, const float* resid) {
        const int C2 = 2 * CC;
        run_conv(Wq + (size_t)li * CC * CC, bq + (size_t)li * CC, x1, nullptr, CC,
                 Q, nullptr, CC, CC, Nq, nullptr, nullptr, 0, nullptr);
        run_conv(Wk + (size_t)li * CC * CC, bk + (size_t)li * CC, x2, nullptr, CC,
                 K, nullptr, CC, CC, Nk, nullptr, nullptr, 0, nullptr);
        run_conv(Wv + (size_t)li * CC * CC, bv + (size_t)li * CC, x2, nullptr, CC,
                 V, nullptr, CC, CC, Nk, nullptr, nullptr, 0, nullptr);

        // choose split count to expose ~750 CTAs
        int qblocks = (Nq + FBQ - 1) / FBQ;
        int nsplit  = 1;
        if (qblocks * BH < 400) nsplit = NSPLIT;
        int nkt = (Nk + FBK - 1) / FBK;
        int kvchunk = ((nkt + nsplit - 1) / nsplit) * FBK;

        dim3 fg(qblocks, BH, nsplit);
        flash_attn<<<fg, 256>>>(Q, K, V, mask, AO, OP, MP, LP, Nq, Nk, nsplit, kvchunk);
        if (nsplit > 1) {
            int tot = BH * Nq;
            flash_combine<<<(tot + 255) / 256, 256>>>(OP, MP, LP, AO, Nq, nsplit);
        }

        run_conv(Wm + (size_t)li * CC * CC, bm + (size_t)li * CC, AO, nullptr, CC,
                 ADD, nullptr, CC, CC, Nq, nullptr, nullptr, 0, nullptr);
        run_conv(Wc1 + (size_t)li * C2 * C2, bc1 + (size_t)li * C2, x1, ADD, CC,
                 Hb, nullptr, C2, C2, Nq, bns + (size_t)li * C2, bnsh + (size_t)li * C2, 1, nullptr);
        run_conv(Wc2 + (size_t)li * CC * C2, bc2 + (size_t)li * CC, Hb, nullptr, C2,
                 out, outPre, CC, C2, Nq, nullptr, nullptr, 0, resid);
    };

    float* dnew   = (float*)d_out;                 // [B,C,N]
    float* logout = dnew + (size_t)BB * CC * NN;   // [B,N]

    // layer 0: cluster  (feat_piece <- d, masked kv)
    attn(feat_piece, d_in1, logits_in, MM, NN, 0, F1, nullptr, feat_piece);
    // layer 1: context  (self-attention on feat)
    attn(F1, F1, nullptr, MM, MM, 1, F2, nullptr, F1);
    // layer 2: decluster (d <- feat); out=dnew (with resid), outPre=XH (= d_new - d_old)
    attn(d_in1, F2, nullptr, NN, MM, 2, dnew, XH, d_in1);

    // head on x = d_new - d_old == XH
    run_conv(iW1, ib1, XH, nullptr, CC, T1, nullptr, 64, CC, NN, nullptr, nullptr, 0, nullptr);
    instnorm_relu<<<BB * 64, 256>>>(T1, ibn1s, ibn1sh, 64, NN);

    conv_small<<<(BB * 16 * NN + 255) / 256, 256>>>(iW2, ib2, T1, T2, 16, 64, NN);
    instnorm_relu<<<BB * 16, 256>>>(T2, ibn2s, ibn2sh, 16, NN);

    conv_small<<<(BB * 4 * NN + 255) / 256, 256>>>(iW3, ib3, T2, T3, 4, 16, NN);
    instnorm_relu<<<BB * 4, 256>>>(T3, ibn3s, ibn3sh, 4, NN);

    conv_small<<<(BB * 1 * NN + 255) / 256, 256>>>(iW4, ib4, T3, logout, 1, 4, NN);
}

// round 4
// speedup vs baseline: 2.7537x; 1.3791x over previous
#include <cuda_runtime.h>
#include <math.h>
#include <stdint.h>

// Problem constants
#define BB 2
#define CC 128
#define NN 6000
#define MM 1500
#define HH 4
#define DHH 32
#define BH (BB*HH)
#define NSPLIT 4

// ---------------- scratch (static device globals; no allocation) ----------------
__device__ float g_Q  [BB*CC*NN];
__device__ float g_K  [BB*CC*NN];
__device__ float g_V  [BB*CC*NN];
__device__ float g_AO [BB*CC*NN];
__device__ float g_ADD[BB*CC*NN];
__device__ float g_Hb [BB*2*CC*NN];
__device__ float g_F1 [BB*CC*MM];
__device__ float g_F2 [BB*CC*MM];
__device__ float g_XH [BB*CC*NN];
__device__ float g_T1 [BB*64*NN];
__device__ float g_T2 [BB*16*NN];
__device__ float g_T3 [BB*4*NN];
// split-KV partials
__device__ float g_OP [NSPLIT*BH*DHH*NN];
__device__ float g_MP [NSPLIT*BH*NN];
__device__ float g_LP [NSPLIT*BH*NN];

// ---------------- tiled fp32 GEMM for 1x1 conv ----------------
#define GBM 64
#define GBN 64
#define GBK 32

__global__ void conv_gemm(const float* __restrict__ W, const float* __restrict__ bias,
                          const float* __restrict__ X1, const float* __restrict__ X2, int split,
                          float* __restrict__ Y, float* __restrict__ Ypre,
                          int Cout, int Cin, int Nlen,
                          const float* __restrict__ scale, const float* __restrict__ shift,
                          int do_relu, const float* __restrict__ resid)
{
    __shared__ float Ws[GBK][GBM + 4];
    __shared__ float Xs[GBK][GBN];

    const int b   = blockIdx.z;
    const int om0 = blockIdx.y * GBM;
    const int n0  = blockIdx.x * GBN;
    const int tid = threadIdx.x;      // 256
    const int tx  = tid & 15;
    const int ty  = tid >> 4;

    float acc[4][4];
#pragma unroll
    for (int i = 0; i < 4; i++)
#pragma unroll
        for (int j = 0; j < 4; j++) acc[i][j] = 0.f;

    for (int k0 = 0; k0 < Cin; k0 += GBK) {
        for (int i = tid; i < GBM * (GBK / 4); i += 256) {
            int o  = i / (GBK / 4);
            int k4 = i % (GBK / 4);
            float4 w = make_float4(0.f, 0.f, 0.f, 0.f);
            if (om0 + o < Cout)
                w = *(const float4*)&W[(size_t)(om0 + o) * Cin + k0 + k4 * 4];
            Ws[k4 * 4 + 0][o] = w.x;
            Ws[k4 * 4 + 1][o] = w.y;
            Ws[k4 * 4 + 2][o] = w.z;
            Ws[k4 * 4 + 3][o] = w.w;
        }
        for (int i = tid; i < GBK * (GBN / 4); i += 256) {
            int kk = i / (GBN / 4);
            int n4 = i % (GBN / 4);
            int c  = k0 + kk;
            int nn = n0 + n4 * 4;
            float4 xv = make_float4(0.f, 0.f, 0.f, 0.f);
            if (nn < Nlen) {
                if (c < split) xv = *(const float4*)&X1[((size_t)b * split + c) * Nlen + nn];
                else           xv = *(const float4*)&X2[((size_t)b * (Cin - split) + (c - split)) * Nlen + nn];
            }
            *(float4*)&Xs[kk][n4 * 4] = xv;
        }
        __syncthreads();
#pragma unroll
        for (int kk = 0; kk < GBK; kk++) {
            float4 rw = *(const float4*)&Ws[kk][ty * 4];
            float4 rx = *(const float4*)&Xs[kk][tx * 4];
            acc[0][0] += rw.x * rx.x; acc[0][1] += rw.x * rx.y; acc[0][2] += rw.x * rx.z; acc[0][3] += rw.x * rx.w;
            acc[1][0] += rw.y * rx.x; acc[1][1] += rw.y * rx.y; acc[1][2] += rw.y * rx.z; acc[1][3] += rw.y * rx.w;
            acc[2][0] += rw.z * rx.x; acc[2][1] += rw.z * rx.y; acc[2][2] += rw.z * rx.z; acc[2][3] += rw.z * rx.w;
            acc[3][0] += rw.w * rx.x; acc[3][1] += rw.w * rx.y; acc[3][2] += rw.w * rx.z; acc[3][3] += rw.w * rx.w;
        }
        __syncthreads();
    }

    const int nn0 = n0 + tx * 4;
#pragma unroll
    for (int i = 0; i < 4; i++) {
        int o = om0 + ty * 4 + i;
        if (o >= Cout) continue;
        float bi = bias  ? bias[o]  : 0.f;
        float sc = scale ? scale[o] : 1.f;
        float sh = shift ? shift[o] : 0.f;
        if (nn0 >= Nlen) continue;
        float4 yv;
        yv.x = (acc[i][0] + bi) * sc + sh;
        yv.y = (acc[i][1] + bi) * sc + sh;
        yv.z = (acc[i][2] + bi) * sc + sh;
        yv.w = (acc[i][3] + bi) * sc + sh;
        if (do_relu) {
            yv.x = fmaxf(yv.x, 0.f); yv.y = fmaxf(yv.y, 0.f);
            yv.z = fmaxf(yv.z, 0.f); yv.w = fmaxf(yv.w, 0.f);
        }
        size_t off = ((size_t)b * Cout + o) * Nlen + nn0;
        if (Ypre) *(float4*)&Ypre[off] = yv;
        if (resid) {
            float4 rv = *(const float4*)&resid[off];
            yv.x += rv.x; yv.y += rv.y; yv.z += rv.z; yv.w += rv.w;
        }
        *(float4*)&Y[off] = yv;
    }
}

// ---------------- tf32 mma helpers ----------------
__device__ __forceinline__ uint32_t f2tf(float f) {
    uint32_t u;
    asm("cvt.rna.tf32.f32 %0, %1;" : "=r"(u) : "f"(f));
    return u;
}
__device__ __forceinline__ float tfb(float f) { return __uint_as_float(f2tf(f)); }

__device__ __forceinline__ void mma8(float* d, const uint32_t* a, const uint32_t* b) {
    asm volatile("mma.sync.aligned.m16n8k8.row.col.f32.tf32.tf32.f32 "
                 "{%0,%1,%2,%3}, {%4,%5,%6,%7}, {%8,%9}, {%0,%1,%2,%3};\n"
                 : "+f"(d[0]), "+f"(d[1]), "+f"(d[2]), "+f"(d[3])
                 : "r"(a[0]), "r"(a[1]), "r"(a[2]), "r"(a[3]),
                   "r"(b[0]), "r"(b[1]));
}

// ---------------- flash attention (tf32 mma, online softmax, split-KV) ----------------
// 128 threads = 4 warps; each warp owns 16 q-rows x 64 kv-cols per tile.
#define FBQ 64
#define FBK 64
#define KSS 72   // ks row stride: (8*t4+g) bank pattern -> conflict-free
#define VSS 40   // vs row stride: same property
#define PSS 68   // ps row stride: (4*g+t4) conflict-free

__global__ void __launch_bounds__(128)
flash_attn_mma(const float* __restrict__ Q, const float* __restrict__ K,
               const float* __restrict__ V, const float* __restrict__ maskLogits,
               float* __restrict__ O,
               float* __restrict__ Opart, float* __restrict__ Mpart, float* __restrict__ Lpart,
               int Nq, int Nk, int nsplit, int kvchunk)
{
    __shared__ float qs[DHH][FBQ];         // Q (tf32 bits), [d][r]
    __shared__ float ks[DHH][KSS];         // K (tf32 bits), [d][c]
    __shared__ float vs[FBK][VSS];         // V (tf32 bits), [c][d]
    __shared__ float ps[4][16][PSS];       // P (tf32 bits), per-warp [r][c]
    __shared__ float ms[FBK];              // mask code: 0 keep, 1 masked, 2 padding

    const int bh = blockIdx.y;
    const int b  = bh / HH;
    const int h  = bh % HH;
    const int q0 = blockIdx.x * FBQ;
    const int sp = blockIdx.z;
    const int tid = threadIdx.x;
    const int w = tid >> 5, lane = tid & 31;
    const int g = lane >> 2, t4 = lane & 3;
    const float sm_scale = 0.17677669529663687f;  // 1/sqrt(32)
    const float MASKV = -1.0e6f * 0.17677669529663687f;

    const float* Qb = Q + ((size_t)b * CC + h * DHH) * Nq;
    const float* Kb = K + ((size_t)b * CC + h * DHH) * Nk;
    const float* Vb = V + ((size_t)b * CC + h * DHH) * Nk;

    // load Q tile -> qs (tf32); Nq % 4 == 0
    for (int i = tid; i < DHH * (FBQ / 4); i += 128) {
        int d  = i / (FBQ / 4);
        int r4 = (i % (FBQ / 4)) * 4;
        int nn = q0 + r4;
        float4 qv = make_float4(0.f, 0.f, 0.f, 0.f);
        if (nn < Nq) qv = *(const float4*)&Qb[(size_t)d * Nq + nn];
        qs[d][r4 + 0] = tfb(qv.x);
        qs[d][r4 + 1] = tfb(qv.y);
        qs[d][r4 + 2] = tfb(qv.z);
        qs[d][r4 + 3] = tfb(qv.w);
    }
    __syncthreads();

    // A(Q^T) fragments: 4 k-steps (d), loaded once
    uint32_t aq[4][4];
    const int qr = w * 16;
#pragma unroll
    for (int s = 0; s < 4; s++) {
        aq[s][0] = __float_as_uint(qs[s * 8 + t4][qr + g]);
        aq[s][1] = __float_as_uint(qs[s * 8 + t4][qr + g + 8]);
        aq[s][2] = __float_as_uint(qs[s * 8 + t4 + 4][qr + g]);
        aq[s][3] = __float_as_uint(qs[s * 8 + t4 + 4][qr + g + 8]);
    }

    float o[4][4];
#pragma unroll
    for (int nt = 0; nt < 4; nt++) { o[nt][0] = o[nt][1] = o[nt][2] = o[nt][3] = 0.f; }
    float m_lo = -3.0e38f, m_hi = -3.0e38f, l_lo = 0.f, l_hi = 0.f;

    const int kvbeg = sp * kvchunk;
    const int kvend = min(Nk, kvbeg + kvchunk);

    for (int k0 = kvbeg; k0 < kvend; k0 += FBK) {
        // mask codes for this tile
        if (tid < FBK) {
            int nn = k0 + tid;
            float f;
            if (nn >= Nk)          f = 2.f;
            else if (maskLogits)   f = (maskLogits[(size_t)b * Nk + nn] > 0.f) ? 0.f : 1.f;
            else                   f = 0.f;
            ms[tid] = f;
        }
        // K,V tiles -> smem (tf32); V transposed; Nk % 4 == 0
        for (int i = tid; i < DHH * (FBK / 4); i += 128) {
            int d  = i / (FBK / 4);
            int c4 = (i % (FBK / 4)) * 4;
            int nn = k0 + c4;
            float4 kv = make_float4(0.f, 0.f, 0.f, 0.f);
            float4 vv = make_float4(0.f, 0.f, 0.f, 0.f);
            if (nn < Nk) {
                kv = *(const float4*)&Kb[(size_t)d * Nk + nn];
                vv = *(const float4*)&Vb[(size_t)d * Nk + nn];
            }
            ks[d][c4 + 0] = tfb(kv.x);
            ks[d][c4 + 1] = tfb(kv.y);
            ks[d][c4 + 2] = tfb(kv.z);
            ks[d][c4 + 3] = tfb(kv.w);
            vs[c4 + 0][d] = tfb(vv.x);
            vs[c4 + 1][d] = tfb(vv.y);
            vs[c4 + 2][d] = tfb(vv.z);
            vs[c4 + 3][d] = tfb(vv.w);
        }
        __syncthreads();

        // ---- S = Q^T K : 8 n-tiles x 4 k-steps ----
        float sv[8][4];
#pragma unroll
        for (int nt = 0; nt < 8; nt++) {
            sv[nt][0] = sv[nt][1] = sv[nt][2] = sv[nt][3] = 0.f;
#pragma unroll
            for (int s = 0; s < 4; s++) {
                uint32_t bf[2];
                bf[0] = __float_as_uint(ks[s * 8 + t4][nt * 8 + g]);
                bf[1] = __float_as_uint(ks[s * 8 + t4 + 4][nt * 8 + g]);
                mma8(sv[nt], aq[s], bf);
            }
        }

        // ---- mask + scale + tile max ----
        float tmax_lo = -3.0e38f, tmax_hi = -3.0e38f;
#pragma unroll
        for (int nt = 0; nt < 8; nt++) {
            float m0 = ms[nt * 8 + 2 * t4];
            float m1 = ms[nt * 8 + 2 * t4 + 1];
            sv[nt][0] = (m0 == 0.f) ? sv[nt][0] * sm_scale : ((m0 == 1.f) ? MASKV : -3.0e38f);
            sv[nt][1] = (m1 == 0.f) ? sv[nt][1] * sm_scale : ((m1 == 1.f) ? MASKV : -3.0e38f);
            sv[nt][2] = (m0 == 0.f) ? sv[nt][2] * sm_scale : ((m0 == 1.f) ? MASKV : -3.0e38f);
            sv[nt][3] = (m1 == 0.f) ? sv[nt][3] * sm_scale : ((m1 == 1.f) ? MASKV : -3.0e38f);
            tmax_lo = fmaxf(tmax_lo, fmaxf(sv[nt][0], sv[nt][1]));
            tmax_hi = fmaxf(tmax_hi, fmaxf(sv[nt][2], sv[nt][3]));
        }
        tmax_lo = fmaxf(tmax_lo, __shfl_xor_sync(0xffffffffu, tmax_lo, 1));
        tmax_lo = fmaxf(tmax_lo, __shfl_xor_sync(0xffffffffu, tmax_lo, 2));
        tmax_hi = fmaxf(tmax_hi, __shfl_xor_sync(0xffffffffu, tmax_hi, 1));
        tmax_hi = fmaxf(tmax_hi, __shfl_xor_sync(0xffffffffu, tmax_hi, 2));

        float mn_lo = fmaxf(m_lo, tmax_lo);
        float mn_hi = fmaxf(m_hi, tmax_hi);
        float corr_lo = __expf(m_lo - mn_lo);
        float corr_hi = __expf(m_hi - mn_hi);
        m_lo = mn_lo; m_hi = mn_hi;

        float rs_lo = 0.f, rs_hi = 0.f;
#pragma unroll
        for (int nt = 0; nt < 8; nt++) {
            float p0 = __expf(sv[nt][0] - mn_lo);
            float p1 = __expf(sv[nt][1] - mn_lo);
            float p2 = __expf(sv[nt][2] - mn_hi);
            float p3 = __expf(sv[nt][3] - mn_hi);
            rs_lo += p0 + p1;
            rs_hi += p2 + p3;
            ps[w][g][nt * 8 + 2 * t4]       = __uint_as_float(f2tf(p0));
            ps[w][g][nt * 8 + 2 * t4 + 1]   = __uint_as_float(f2tf(p1));
            ps[w][g + 8][nt * 8 + 2 * t4]     = __uint_as_float(f2tf(p2));
            ps[w][g + 8][nt * 8 + 2 * t4 + 1] = __uint_as_float(f2tf(p3));
        }
        rs_lo += __shfl_xor_sync(0xffffffffu, rs_lo, 1);
        rs_lo += __shfl_xor_sync(0xffffffffu, rs_lo, 2);
        rs_hi += __shfl_xor_sync(0xffffffffu, rs_hi, 1);
        rs_hi += __shfl_xor_sync(0xffffffffu, rs_hi, 2);
        l_lo = l_lo * corr_lo + rs_lo;
        l_hi = l_hi * corr_hi + rs_hi;
#pragma unroll
        for (int nt = 0; nt < 4; nt++) {
            o[nt][0] *= corr_lo; o[nt][1] *= corr_lo;
            o[nt][2] *= corr_hi; o[nt][3] *= corr_hi;
        }
        __syncwarp();

        // ---- A(P) fragments: 8 k-steps (c) ----
        uint32_t ap[8][4];
#pragma unroll
        for (int s = 0; s < 8; s++) {
            ap[s][0] = __float_as_uint(ps[w][g][s * 8 + t4]);
            ap[s][1] = __float_as_uint(ps[w][g + 8][s * 8 + t4]);
            ap[s][2] = __float_as_uint(ps[w][g][s * 8 + t4 + 4]);
            ap[s][3] = __float_as_uint(ps[w][g + 8][s * 8 + t4 + 4]);
        }
        // ---- O += P V : 4 n-tiles (d) x 8 k-steps ----
#pragma unroll
        for (int nt = 0; nt < 4; nt++) {
#pragma unroll
            for (int s = 0; s < 8; s++) {
                uint32_t bf[2];
                bf[0] = __float_as_uint(vs[s * 8 + t4][nt * 8 + g]);
                bf[1] = __float_as_uint(vs[s * 8 + t4 + 4][nt * 8 + g]);
                mma8(o[nt], ap[s], bf);
            }
        }
        __syncthreads();
    }

    const int r_lo = q0 + w * 16 + g;
    const int r_hi = r_lo + 8;
    if (nsplit == 1) {
        float* Ob = O + ((size_t)b * CC + h * DHH) * Nq;
        float il_lo = 1.f / l_lo, il_hi = 1.f / l_hi;
#pragma unroll
        for (int nt = 0; nt < 4; nt++) {
            int d0 = nt * 8 + 2 * t4;
            if (r_lo < Nq) {
                Ob[(size_t)d0 * Nq + r_lo]       = o[nt][0] * il_lo;
                Ob[(size_t)(d0 + 1) * Nq + r_lo] = o[nt][1] * il_lo;
            }
            if (r_hi < Nq) {
                Ob[(size_t)d0 * Nq + r_hi]       = o[nt][2] * il_hi;
                Ob[(size_t)(d0 + 1) * Nq + r_hi] = o[nt][3] * il_hi;
            }
        }
    } else {
        float* Op = Opart + ((size_t)sp * BH + bh) * DHH * Nq;
#pragma unroll
        for (int nt = 0; nt < 4; nt++) {
            int d0 = nt * 8 + 2 * t4;
            if (r_lo < Nq) {
                Op[(size_t)d0 * Nq + r_lo]       = o[nt][0];
                Op[(size_t)(d0 + 1) * Nq + r_lo] = o[nt][1];
            }
            if (r_hi < Nq) {
                Op[(size_t)d0 * Nq + r_hi]       = o[nt][2];
                Op[(size_t)(d0 + 1) * Nq + r_hi] = o[nt][3];
            }
        }
        if (t4 == 0) {
            size_t base = ((size_t)sp * BH + bh) * Nq;
            if (r_lo < Nq) { Mpart[base + r_lo] = m_lo; Lpart[base + r_lo] = l_lo; }
            if (r_hi < Nq) { Mpart[base + r_hi] = m_hi; Lpart[base + r_hi] = l_hi; }
        }
    }
}

__global__ void flash_combine(const float* __restrict__ Opart, const float* __restrict__ Mpart,
                              const float* __restrict__ Lpart, float* __restrict__ O,
                              int Nq, int nsplit)
{
    int idx = blockIdx.x * blockDim.x + threadIdx.x;
    if (idx >= BH * Nq) return;
    int n  = idx % Nq;
    int bh = idx / Nq;
    int b  = bh / HH;
    int h  = bh % HH;

    float M = -3.0e38f;
    for (int s = 0; s < nsplit; s++)
        M = fmaxf(M, Mpart[((size_t)s * BH + bh) * Nq + n]);
    float w[NSPLIT];
    float L = 0.f;
    for (int s = 0; s < nsplit; s++) {
        float ws = __expf(Mpart[((size_t)s * BH + bh) * Nq + n] - M);
        w[s] = ws;
        L += ws * Lpart[((size_t)s * BH + bh) * Nq + n];
    }
    float inv = 1.f / L;
    float* Ob = O + ((size_t)b * CC + h * DHH) * Nq + n;
    for (int d = 0; d < DHH; d++) {
        float acc = 0.f;
        for (int s = 0; s < nsplit; s++)
            acc += w[s] * Opart[(((size_t)s * BH + bh) * DHH + d) * Nq + n];
        Ob[(size_t)d * Nq] = acc * inv;
    }
}

// ---------------- small conv (Cout small: 16/4/1) ----------------
__global__ void conv_small(const float* __restrict__ W, const float* __restrict__ bias,
                           const float* __restrict__ X, float* __restrict__ Y,
                           int Cout, int Cin, int Nlen)
{
    int idx = blockIdx.x * blockDim.x + threadIdx.x;
    int total = BB * Cout * Nlen;
    if (idx >= total) return;
    int n = idx % Nlen;
    int o = (idx / Nlen) % Cout;
    int b = idx / (Nlen * Cout);
    float acc = bias[o];
    const float* Xb = X + (size_t)b * Cin * Nlen + n;
    const float* Wo = W + (size_t)o * Cin;
    for (int c = 0; c < Cin; c++) acc += Wo[c] * Xb[(size_t)c * Nlen];
    Y[idx] = acc;
}

// ---------------- instance norm + scale/shift + relu, in place ----------------
__global__ void instnorm_relu(float* __restrict__ X, const float* __restrict__ s,
                              const float* __restrict__ sh, int Cc, int Nlen)
{
    int bc = blockIdx.x;
    int c  = bc % Cc;
    float* x = X + (size_t)bc * Nlen;
    int tid = threadIdx.x;

    float sum = 0.f, sq = 0.f;
    for (int i = tid; i < Nlen; i += blockDim.x) { float v = x[i]; sum += v; sq += v * v; }
#pragma unroll
    for (int off = 16; off >= 1; off >>= 1) {
        sum += __shfl_xor_sync(0xffffffffu, sum, off);
        sq  += __shfl_xor_sync(0xffffffffu, sq,  off);
    }
    __shared__ float ssum[8], ssq[8];
    __shared__ float smu, sinv;
    int w = tid >> 5;
    if ((tid & 31) == 0) { ssum[w] = sum; ssq[w] = sq; }
    __syncthreads();
    if (tid == 0) {
        float S = 0.f, Q2 = 0.f;
        for (int i = 0; i < (int)(blockDim.x >> 5); i++) { S += ssum[i]; Q2 += ssq[i]; }
        float mu  = S / Nlen;
        float var = fmaxf(Q2 / Nlen - mu * mu, 0.f);
        smu  = mu;
        sinv = rsqrtf(var + 1e-3f);
    }
    __syncthreads();
    float scv = s[c] * sinv, mu = smu, shv = sh[c];
    for (int i = tid; i < Nlen; i += blockDim.x) {
        float v = (x[i] - mu) * scv + shv;
        x[i] = fmaxf(v, 0.f);
    }
}

// ---------------- host ----------------
static void run_conv(const float* W, const float* bias,
                     const float* X1, const float* X2, int split,
                     float* Y, float* Ypre, int Cout, int Cin, int Nlen,
                     const float* scale, const float* shift, int relu, const float* resid)
{
    dim3 grid((Nlen + GBN - 1) / GBN, (Cout + GBM - 1) / GBM, BB);
    conv_gemm<<<grid, 256>>>(W, bias, X1, X2, split, Y, Ypre, Cout, Cin, Nlen, scale, shift, relu, resid);
}

extern "C" void kernel_launch(void* const* d_in, const int* in_sizes, int n_in,
                              void* d_out, int out_size)
{
    const float* d_in1      = (const float*)d_in[1];
    const float* feat_piece = (const float*)d_in[2];
    const float* logits_in  = (const float*)d_in[3];
    const float* Wq  = (const float*)d_in[4];
    const float* bq  = (const float*)d_in[5];
    const float* Wk  = (const float*)d_in[6];
    const float* bk  = (const float*)d_in[7];
    const float* Wv  = (const float*)d_in[8];
    const float* bv  = (const float*)d_in[9];
    const float* Wm  = (const float*)d_in[10];
    const float* bm  = (const float*)d_in[11];
    const float* Wc1 = (const float*)d_in[12];
    const float* bc1 = (const float*)d_in[13];
    const float* bns = (const float*)d_in[14];
    const float* bnsh= (const float*)d_in[15];
    const float* Wc2 = (const float*)d_in[16];
    const float* bc2 = (const float*)d_in[17];
    const float* iW1 = (const float*)d_in[18];
    const float* ib1 = (const float*)d_in[19];
    const float* ibn1s  = (const float*)d_in[20];
    const float* ibn1sh = (const float*)d_in[21];
    const float* iW2 = (const float*)d_in[22];
    const float* ib2 = (const float*)d_in[23];
    const float* ibn2s  = (const float*)d_in[24];
    const float* ibn2sh = (const float*)d_in[25];
    const float* iW3 = (const float*)d_in[26];
    const float* ib3 = (const float*)d_in[27];
    const float* ibn3s  = (const float*)d_in[28];
    const float* ibn3sh = (const float*)d_in[29];
    const float* iW4 = (const float*)d_in[30];
    const float* ib4 = (const float*)d_in[31];

    float *Q, *K, *V, *AO, *ADD, *Hb, *F1, *F2, *XH, *T1, *T2, *T3, *OP, *MP, *LP;
    cudaGetSymbolAddress((void**)&Q,   g_Q);
    cudaGetSymbolAddress((void**)&K,   g_K);
    cudaGetSymbolAddress((void**)&V,   g_V);
    cudaGetSymbolAddress((void**)&AO,  g_AO);
    cudaGetSymbolAddress((void**)&ADD, g_ADD);
    cudaGetSymbolAddress((void**)&Hb,  g_Hb);
    cudaGetSymbolAddress((void**)&F1,  g_F1);
    cudaGetSymbolAddress((void**)&F2,  g_F2);
    cudaGetSymbolAddress((void**)&XH,  g_XH);
    cudaGetSymbolAddress((void**)&T1,  g_T1);
    cudaGetSymbolAddress((void**)&T2,  g_T2);
    cudaGetSymbolAddress((void**)&T3,  g_T3);
    cudaGetSymbolAddress((void**)&OP,  g_OP);
    cudaGetSymbolAddress((void**)&MP,  g_MP);
    cudaGetSymbolAddress((void**)&LP,  g_LP);

    auto attn = [&](const float* x1, const float* x2, const float* mask,
                    int Nq, int Nk, int li, float* out, float* outPre, const float* resid) {
        const int C2 = 2 * CC;
        run_conv(Wq + (size_t)li * CC * CC, bq + (size_t)li * CC, x1, nullptr, CC,
                 Q, nullptr, CC, CC, Nq, nullptr, nullptr, 0, nullptr);
        run_conv(Wk + (size_t)li * CC * CC, bk + (size_t)li * CC, x2, nullptr, CC,
                 K, nullptr, CC, CC, Nk, nullptr, nullptr, 0, nullptr);
        run_conv(Wv + (size_t)li * CC * CC, bv + (size_t)li * CC, x2, nullptr, CC,
                 V, nullptr, CC, CC, Nk, nullptr, nullptr, 0, nullptr);

        int qblocks = (Nq + FBQ - 1) / FBQ;
        int nsplit  = 1;
        if (qblocks * BH < 400) nsplit = NSPLIT;
        int nkt = (Nk + FBK - 1) / FBK;
        int kvchunk = ((nkt + nsplit - 1) / nsplit) * FBK;

        dim3 fg(qblocks, BH, nsplit);
        flash_attn_mma<<<fg, 128>>>(Q, K, V, mask, AO, OP, MP, LP, Nq, Nk, nsplit, kvchunk);
        if (nsplit > 1) {
            int tot = BH * Nq;
            flash_combine<<<(tot + 255) / 256, 256>>>(OP, MP, LP, AO, Nq, nsplit);
        }

        run_conv(Wm + (size_t)li * CC * CC, bm + (size_t)li * CC, AO, nullptr, CC,
                 ADD, nullptr, CC, CC, Nq, nullptr, nullptr, 0, nullptr);
        run_conv(Wc1 + (size_t)li * C2 * C2, bc1 + (size_t)li * C2, x1, ADD, CC,
                 Hb, nullptr, C2, C2, Nq, bns + (size_t)li * C2, bnsh + (size_t)li * C2, 1, nullptr);
        run_conv(Wc2 + (size_t)li * CC * C2, bc2 + (size_t)li * CC, Hb, nullptr, C2,
                 out, outPre, CC, C2, Nq, nullptr, nullptr, 0, resid);
    };

    float* dnew   = (float*)d_out;                 // [B,C,N]
    float* logout = dnew + (size_t)BB * CC * NN;   // [B,N]

    attn(feat_piece, d_in1, logits_in, MM, NN, 0, F1, nullptr, feat_piece);
    attn(F1, F1, nullptr, MM, MM, 1, F2, nullptr, F1);
    attn(d_in1, F2, nullptr, NN, MM, 2, dnew, XH, d_in1);

    run_conv(iW1, ib1, XH, nullptr, CC, T1, nullptr, 64, CC, NN, nullptr, nullptr, 0, nullptr);
    instnorm_relu<<<BB * 64, 256>>>(T1, ibn1s, ibn1sh, 64, NN);

    conv_small<<<(BB * 16 * NN + 255) / 256, 256>>>(iW2, ib2, T1, T2, 16, 64, NN);
    instnorm_relu<<<BB * 16, 256>>>(T2, ibn2s, ibn2sh, 16, NN);

    conv_small<<<(BB * 4 * NN + 255) / 256, 256>>>(iW3, ib3, T2, T3, 4, 16, NN);
    instnorm_relu<<<BB * 4, 256>>>(T3, ibn3s, ibn3sh, 4, NN);

    conv_small<<<(BB * 1 * NN + 255) / 256, 256>>>(iW4, ib4, T3, logout, 1, 4, NN);
}